// round 4
// baseline (speedup 1.0000x reference)
#include <cuda_runtime.h>

// Problem constants: T=1024, B=64, I=512, H=512, 3H=1536
#define NCTA 128   // persistent recurrent kernel grid (<= 148 SMs -> all co-resident)

// ---------------- device-global scratch (no allocation allowed) ----------------
__device__ float g_gx[100663296];                       // [1024*64, 1536] input gate pre-acts
__device__ __align__(16) float g_hT[2][32768];          // ping-pong TRANSPOSED h: [512 units][64 b]
__device__ unsigned int g_bar_cnt = 0;
__device__ volatile unsigned int g_bar_gen = 0;

// ---------------- f32x2 packed-math helpers (Blackwell, PTX-only path) ----------
__device__ __forceinline__ void ffma2(unsigned long long &acc, unsigned long long a,
                                      unsigned long long b) {
    asm("fma.rn.f32x2 %0, %1, %2, %0;" : "+l"(acc) : "l"(a), "l"(b));
}
__device__ __forceinline__ unsigned long long dup2(float a) {
    unsigned long long r; asm("mov.b64 %0, {%1, %1};" : "=l"(r) : "f"(a)); return r;
}
__device__ __forceinline__ unsigned long long pack2(float lo, float hi) {
    unsigned long long r; asm("mov.b64 %0, {%1, %2};" : "=l"(r) : "f"(lo), "f"(hi)); return r;
}
__device__ __forceinline__ float2 unpack2(unsigned long long v) {
    float2 f; asm("mov.b64 {%0, %1}, %2;" : "=f"(f.x), "=f"(f.y) : "l"(v)); return f;
}

// ---------------- software grid barrier (all NCTA CTAs resident) ----------------
// __threadfence() (gpu scope) emits CCTL.IVALL -> flushes L1D, so post-barrier
// LDGs observe other SMs' h writes through L2. Load-bearing for correctness.
__device__ __forceinline__ void grid_sync() {
    __threadfence();
    __syncthreads();
    if (threadIdx.x == 0) {
        unsigned int gen = g_bar_gen;
        if (atomicAdd(&g_bar_cnt, 1u) == NCTA - 1) {
            g_bar_cnt = 0;
            __threadfence();
            g_bar_gen = gen + 1;
        } else {
            while (g_bar_gen == gen) { __nanosleep(32); }
        }
        __threadfence();
    }
    __syncthreads();
}

// =================================================================================
// Kernel A: gx[m][n] = sum_k X[m][k] * W[n][k] + bias[n]
//   X: [65536, 512], W: [1536, 512] -> g_gx. 128x128 tile, BK=8, 8x8 microtile.
// =================================================================================
__global__ __launch_bounds__(256) void gemm_gx(const float* __restrict__ X,
                                               const float* __restrict__ W,
                                               const float* __restrict__ bias) {
    __shared__ __align__(16) float As[8][128];
    __shared__ __align__(16) float Bs[8][128];
    const int tid = threadIdx.x;
    const int m0 = blockIdx.y * 128;
    const int n0 = blockIdx.x * 128;
    const int tx = tid & 15;
    const int ty = tid >> 4;
    const int lrow = tid >> 1;
    const int lk = (tid & 1) * 4;

    unsigned long long acc[8][4];
#pragma unroll
    for (int i = 0; i < 8; i++)
#pragma unroll
        for (int jp = 0; jp < 4; jp++) acc[i][jp] = 0ull;

    const float* xg = X + (size_t)(m0 + lrow) * 512 + lk;
    const float* wg = W + (size_t)(n0 + lrow) * 512 + lk;

    for (int k0 = 0; k0 < 512; k0 += 8) {
        float4 av = *(const float4*)(xg + k0);
        float4 bv = *(const float4*)(wg + k0);
        __syncthreads();
        As[lk + 0][lrow] = av.x; As[lk + 1][lrow] = av.y;
        As[lk + 2][lrow] = av.z; As[lk + 3][lrow] = av.w;
        Bs[lk + 0][lrow] = bv.x; Bs[lk + 1][lrow] = bv.y;
        Bs[lk + 2][lrow] = bv.z; Bs[lk + 3][lrow] = bv.w;
        __syncthreads();
#pragma unroll
        for (int kk = 0; kk < 8; kk++) {
            float4 a0 = *(const float4*)&As[kk][ty * 8];
            float4 a1 = *(const float4*)&As[kk][ty * 8 + 4];
            float4 b0 = *(const float4*)&Bs[kk][tx * 8];
            float4 b1 = *(const float4*)&Bs[kk][tx * 8 + 4];
            unsigned long long bp0 = pack2(b0.x, b0.y);
            unsigned long long bp1 = pack2(b0.z, b0.w);
            unsigned long long bp2 = pack2(b1.x, b1.y);
            unsigned long long bp3 = pack2(b1.z, b1.w);
            float a[8] = {a0.x, a0.y, a0.z, a0.w, a1.x, a1.y, a1.z, a1.w};
#pragma unroll
            for (int i = 0; i < 8; i++) {
                unsigned long long ad = dup2(a[i]);
                ffma2(acc[i][0], ad, bp0);
                ffma2(acc[i][1], ad, bp1);
                ffma2(acc[i][2], ad, bp2);
                ffma2(acc[i][3], ad, bp3);
            }
        }
    }

    float bs[8];
#pragma unroll
    for (int c = 0; c < 8; c++) bs[c] = bias[n0 + tx * 8 + c];
#pragma unroll
    for (int i = 0; i < 8; i++) {
        size_t base = (size_t)(m0 + ty * 8 + i) * 1536 + n0 + tx * 8;
        float2 p0 = unpack2(acc[i][0]);
        float2 p1 = unpack2(acc[i][1]);
        float2 p2 = unpack2(acc[i][2]);
        float2 p3 = unpack2(acc[i][3]);
        float4 o0 = make_float4(p0.x + bs[0], p0.y + bs[1], p1.x + bs[2], p1.y + bs[3]);
        float4 o1 = make_float4(p2.x + bs[4], p2.y + bs[5], p3.x + bs[6], p3.y + bs[7]);
        *(float4*)&g_gx[base]     = o0;
        *(float4*)&g_gx[base + 4] = o1;
    }
}

// =================================================================================
// Kernel B: persistent GRU recurrence, FMA-bound layout.
//   128 CTAs x 256 threads. CTA owns 4 hidden units (12 gate-rows r/z/n x 4).
//   K=512 split across 8 warps (64 each). Lane owns b-pair (2l, 2l+1) x all 12 rows:
//   per k: 1 coalesced LDG.64 of h-pair (transposed layout) + broadcast w from SMEM
//   -> 12 FFMA2. Cross-warp K-reduction via 24KB SMEM, then gate math.
// =================================================================================
__global__ __launch_bounds__(256) void gru_rec(const float* __restrict__ whh,
                                               const float* __restrict__ bhh,
                                               const int* __restrict__ lens,
                                               float* __restrict__ out) {
    __shared__ __align__(16) float w_s[12][512];    // 24KB: row = gate*4 + unit
    __shared__ __align__(16) float red[8][64][12];  // 24KB: [warp][b][row] partials

    const int tid  = threadIdx.x;
    const int cta  = blockIdx.x;
    const int warp = tid >> 5;
    const int lane = tid & 31;
    const int gb = tid >> 2;          // gate-phase batch 0..63
    const int gu = tid & 3;           // gate-phase unit-in-CTA 0..3
    const int j  = cta * 4 + gu;      // global unit

    // Preload W_hh slice (persistent across all 1024 steps)
    for (int q = tid; q < 12 * 128; q += 256) {
        int row = q >> 7;
        int kq  = (q & 127) << 2;
        int g   = row >> 2;
        int u   = row & 3;
        *(float4*)&w_s[row][kq] =
            *(const float4*)&whh[(size_t)(g * 512 + cta * 4 + u) * 512 + kq];
    }

    const float bh_r = bhh[j];
    const float bh_z = bhh[512 + j];
    const float bh_n = bhh[1024 + j];
    const int len_b = lens[gb];

    float hreg = 0.f;
    g_hT[0][j * 64 + gb] = 0.f;       // h0 = 0 (re-done every launch: graph-replay safe)
    __syncthreads();
    grid_sync();

    const int ks = warp * 64;         // this warp's K slice

    for (int t = 0; t < 1024; t++) {
        // Prefetch input-side gates early (latency hidden behind the k-loop)
        const float* gxp = g_gx + (size_t)(t * 64 + gb) * 1536 + j;
        float gxr = gxp[0];
        float gxz = gxp[512];
        float gxn = gxp[1024];

        const float* hc = g_hT[t & 1] + (size_t)ks * 64 + 2 * lane;

        unsigned long long acc[12];
#pragma unroll
        for (int r = 0; r < 12; r++) acc[r] = 0ull;

#pragma unroll 4
        for (int kq = 0; kq < 16; kq++) {
            // 4 coalesced h b-pair loads (h_T[k][b]: 8B per lane, contiguous across warp)
            unsigned long long h0 = *(const unsigned long long*)(hc + (kq * 4 + 0) * 64);
            unsigned long long h1 = *(const unsigned long long*)(hc + (kq * 4 + 1) * 64);
            unsigned long long h2 = *(const unsigned long long*)(hc + (kq * 4 + 2) * 64);
            unsigned long long h3 = *(const unsigned long long*)(hc + (kq * 4 + 3) * 64);
#pragma unroll
            for (int r = 0; r < 12; r++) {
                float4 wv = *(const float4*)&w_s[r][ks + kq * 4];  // broadcast LDS.128
                ffma2(acc[r], h0, dup2(wv.x));
                ffma2(acc[r], h1, dup2(wv.y));
                ffma2(acc[r], h2, dup2(wv.z));
                ffma2(acc[r], h3, dup2(wv.w));
            }
        }

        // Fold b-pair partials into SMEM: red[warp][b][row]
        const int b0 = 2 * lane;
#pragma unroll
        for (int r = 0; r < 12; r++) {
            float2 p = unpack2(acc[r]);
            red[warp][b0][r]     = p.x;
            red[warp][b0 + 1][r] = p.y;
        }
        __syncthreads();

        // Gate phase: reduce 8 warp partials, apply GRU cell
        float ghr = bh_r, ghz = bh_z, ghn = bh_n;
#pragma unroll
        for (int w = 0; w < 8; w++) {
            ghr += red[w][gb][gu];
            ghz += red[w][gb][4 + gu];
            ghn += red[w][gb][8 + gu];
        }

        float r = 1.f / (1.f + __expf(-(gxr + ghr)));
        float z = 1.f / (1.f + __expf(-(gxz + ghz)));
        float n = tanhf(gxn + r * ghn);
        float hnew = (1.f - z) * n + z * hreg;

        bool act = (t < len_b);
        out[(size_t)t * 32768 + gb * 512 + j] = act ? hnew : 0.f;
        if (act) hreg = hnew;
        g_hT[(t + 1) & 1][j * 64 + gb] = hreg;   // transposed write, coalesced-ish

        grid_sync();   // h writes visible (incl. L1 flush) before next step reads
    }

    // h_last: [1, B, H] appended after output
    out[(size_t)1024 * 32768 + gb * 512 + j] = hreg;
}

// =================================================================================
// Inputs (metadata order): x[T,B,I] f32, batch_lengths[B] i32, w_ih[3H,I] f32,
// w_hh[3H,H] f32, b_ih[3H] f32, b_hh[3H] f32.  Output: [T,B,H] then [1,B,H], fp32.
// =================================================================================
extern "C" void kernel_launch(void* const* d_in, const int* in_sizes, int n_in,
                              void* d_out, int out_size) {
    const float* x   = (const float*)d_in[0];
    const int*   len = (const int*)  d_in[1];
    const float* wih = (const float*)d_in[2];
    const float* whh = (const float*)d_in[3];
    const float* bih = (const float*)d_in[4];
    const float* bhh = (const float*)d_in[5];
    float* out = (float*)d_out;

    (void)in_sizes; (void)n_in; (void)out_size;

    gemm_gx<<<dim3(12, 512), 256>>>(x, wih, bih);
    gru_rec<<<NCTA, 256>>>(whh, bhh, len, out);
}

// round 5
// speedup vs baseline: 1.1268x; 1.1268x over previous
#include <cuda_runtime.h>

// Problem constants: T=1024, B=64, I=512, H=512, 3H=1536
#define NCTA 128   // persistent recurrent kernel grid (<= 148 SMs -> all co-resident)

// ---------------- device-global scratch (no allocation allowed) ----------------
__device__ float g_gx[100663296];                       // [1024*64, 1536] input gate pre-acts
__device__ __align__(16) float g_hT[2][32768];          // ping-pong TRANSPOSED h: [512 units][64 b]
__device__ unsigned int g_cnt = 0;                      // barrier arrive counter
__device__ unsigned int g_gen = 0;                      // barrier generation (monotonic)

// ---------------- f32x2 packed-math helpers (Blackwell, PTX-only path) ----------
__device__ __forceinline__ void ffma2(unsigned long long &acc, unsigned long long a,
                                      unsigned long long b) {
    asm("fma.rn.f32x2 %0, %1, %2, %0;" : "+l"(acc) : "l"(a), "l"(b));
}
__device__ __forceinline__ unsigned long long dup2(float a) {
    unsigned long long r; asm("mov.b64 %0, {%1, %1};" : "=l"(r) : "f"(a)); return r;
}
__device__ __forceinline__ unsigned long long pack2(float lo, float hi) {
    unsigned long long r; asm("mov.b64 %0, {%1, %2};" : "=l"(r) : "f"(lo), "f"(hi)); return r;
}
__device__ __forceinline__ float sum2(unsigned long long v) {
    float lo, hi; asm("mov.b64 {%0, %1}, %2;" : "=f"(lo), "=f"(hi) : "l"(v)); return lo + hi;
}
__device__ __forceinline__ float2 unpack2(unsigned long long v) {
    float2 f; asm("mov.b64 {%0, %1}, %2;" : "=f"(f.x), "=f"(f.y) : "l"(v)); return f;
}

// ---------------- fence-free grid barrier (acq/rel atomics, no CCTL.IVALL) -------
// All cross-step h traffic goes through L2 via __ldcg/__stcg, so no L1 flush is
// needed. Arrive = atom.acq_rel (cumulative release of this CTA's writes, which
// happen-before via __syncthreads). Poll = ld.acquire on the generation word.
__device__ __forceinline__ void grid_sync() {
    __syncthreads();
    if (threadIdx.x == 0) {
        unsigned int gen;
        asm volatile("ld.relaxed.gpu.global.u32 %0, [%1];"
                     : "=r"(gen) : "l"(&g_gen) : "memory");
        unsigned int old;
        asm volatile("atom.acq_rel.gpu.global.add.u32 %0, [%1], 1;"
                     : "=r"(old) : "l"(&g_cnt) : "memory");
        if (old == NCTA - 1) {
            asm volatile("st.relaxed.gpu.global.u32 [%0], %1;"
                         :: "l"(&g_cnt), "r"(0u) : "memory");
            asm volatile("st.release.gpu.global.u32 [%0], %1;"
                         :: "l"(&g_gen), "r"(gen + 1u) : "memory");
        } else {
            unsigned int v;
            do {
                asm volatile("ld.acquire.gpu.global.u32 %0, [%1];"
                             : "=r"(v) : "l"(&g_gen) : "memory");
            } while (v == gen);
        }
    }
    __syncthreads();
}

// =================================================================================
// Kernel A: gx[m][n] = sum_k X[m][k] * W[n][k] + bias[n]
//   X: [65536, 512], W: [1536, 512] -> g_gx. 128x128 tile, BK=8, 8x8 microtile.
// =================================================================================
__global__ __launch_bounds__(256) void gemm_gx(const float* __restrict__ X,
                                               const float* __restrict__ W,
                                               const float* __restrict__ bias) {
    __shared__ __align__(16) float As[8][128];
    __shared__ __align__(16) float Bs[8][128];
    const int tid = threadIdx.x;
    const int m0 = blockIdx.y * 128;
    const int n0 = blockIdx.x * 128;
    const int tx = tid & 15;
    const int ty = tid >> 4;
    const int lrow = tid >> 1;
    const int lk = (tid & 1) * 4;

    unsigned long long acc[8][4];
#pragma unroll
    for (int i = 0; i < 8; i++)
#pragma unroll
        for (int jp = 0; jp < 4; jp++) acc[i][jp] = 0ull;

    const float* xg = X + (size_t)(m0 + lrow) * 512 + lk;
    const float* wg = W + (size_t)(n0 + lrow) * 512 + lk;

    for (int k0 = 0; k0 < 512; k0 += 8) {
        float4 av = *(const float4*)(xg + k0);
        float4 bv = *(const float4*)(wg + k0);
        __syncthreads();
        As[lk + 0][lrow] = av.x; As[lk + 1][lrow] = av.y;
        As[lk + 2][lrow] = av.z; As[lk + 3][lrow] = av.w;
        Bs[lk + 0][lrow] = bv.x; Bs[lk + 1][lrow] = bv.y;
        Bs[lk + 2][lrow] = bv.z; Bs[lk + 3][lrow] = bv.w;
        __syncthreads();
#pragma unroll
        for (int kk = 0; kk < 8; kk++) {
            float4 a0 = *(const float4*)&As[kk][ty * 8];
            float4 a1 = *(const float4*)&As[kk][ty * 8 + 4];
            float4 b0 = *(const float4*)&Bs[kk][tx * 8];
            float4 b1 = *(const float4*)&Bs[kk][tx * 8 + 4];
            unsigned long long bp0 = pack2(b0.x, b0.y);
            unsigned long long bp1 = pack2(b0.z, b0.w);
            unsigned long long bp2 = pack2(b1.x, b1.y);
            unsigned long long bp3 = pack2(b1.z, b1.w);
            float a[8] = {a0.x, a0.y, a0.z, a0.w, a1.x, a1.y, a1.z, a1.w};
#pragma unroll
            for (int i = 0; i < 8; i++) {
                unsigned long long ad = dup2(a[i]);
                ffma2(acc[i][0], ad, bp0);
                ffma2(acc[i][1], ad, bp1);
                ffma2(acc[i][2], ad, bp2);
                ffma2(acc[i][3], ad, bp3);
            }
        }
    }

    float bs[8];
#pragma unroll
    for (int c = 0; c < 8; c++) bs[c] = bias[n0 + tx * 8 + c];
#pragma unroll
    for (int i = 0; i < 8; i++) {
        size_t base = (size_t)(m0 + ty * 8 + i) * 1536 + n0 + tx * 8;
        float2 p0 = unpack2(acc[i][0]);
        float2 p1 = unpack2(acc[i][1]);
        float2 p2 = unpack2(acc[i][2]);
        float2 p3 = unpack2(acc[i][3]);
        float4 o0 = make_float4(p0.x + bs[0], p0.y + bs[1], p1.x + bs[2], p1.y + bs[3]);
        float4 o1 = make_float4(p2.x + bs[4], p2.y + bs[5], p3.x + bs[6], p3.y + bs[7]);
        *(float4*)&g_gx[base]     = o0;
        *(float4*)&g_gx[base + 4] = o1;
    }
}

// =================================================================================
// Kernel B: persistent GRU recurrence, k-parity FFMA2 (no operand dup).
//   128 CTAs x 512 threads (16 warps). CTA owns 4 units (12 gate-rows).
//   Warp = (k-slice of 64) x (b-half of 32). Lane = (b-pair p, k-sub of 32).
//   acc2 packs (k, k+1): w operand read directly from SMEM as u64 (contiguous),
//   h pairs repacked with 4 pack2 per 4k. Warp skips accumulate when its whole
//   b-half is past sequence end (lengths are descending-sorted).
// =================================================================================
__global__ __launch_bounds__(512) void gru_rec(const float* __restrict__ whh,
                                               const float* __restrict__ bhh,
                                               const int* __restrict__ lens,
                                               float* __restrict__ out) {
    __shared__ __align__(16) float w_s[12][16][36]; // [row][k-chunk of 32][32+4 pad]
    __shared__ __align__(16) float red[8][64][13];  // [k-slice][b][row(12)+pad]
    __shared__ int lens_s[64];

    const int tid  = threadIdx.x;
    const int cta  = blockIdx.x;
    const int wrp  = tid >> 5;
    const int lane = tid & 31;
    const int kslice = wrp >> 1;            // 0..7 (64 k each)
    const int bhalf  = wrp & 1;             // 0..1 (32 b each)
    const int p      = lane & 15;           // b-pair within half
    const int ksub   = lane >> 4;           // 0..1 (32 k each)
    const int b0     = bhalf * 32 + 2 * p;
    const int k0     = kslice * 64 + ksub * 32;
    const int chunk  = kslice * 2 + ksub;   // w_s chunk index

    // gate-phase mapping (tid < 256): gu slow, gb fast -> coalesced h_T writes
    const int gu = tid >> 6;                // unit-in-CTA 0..3
    const int gb = tid & 63;                // batch 0..63
    const int j  = cta * 4 + gu;            // global unit

    // Preload W_hh slice into chunked/padded SMEM (persistent across steps)
    for (int idx = tid; idx < 12 * 512; idx += 512) {
        int row = idx >> 9;
        int k   = idx & 511;
        int g   = row >> 2;
        int u   = row & 3;
        w_s[row][k >> 5][k & 31] = whh[(size_t)(g * 512 + cta * 4 + u) * 512 + k];
    }
    if (tid < 64) lens_s[tid] = lens[tid];

    float bh_r = 0.f, bh_z = 0.f, bh_n = 0.f;
    int len_b = 0;
    if (tid < 256) {
        bh_r = bhh[j];
        bh_z = bhh[512 + j];
        bh_n = bhh[1024 + j];
        len_b = lens[gb];
        __stcg(&g_hT[0][(size_t)j * 64 + gb], 0.f);   // h0 = 0 (graph-replay safe)
    }
    __syncthreads();
    const int maxlen_half = lens_s[bhalf * 32];       // descending-sorted lengths
    float hreg = 0.f;
    grid_sync();                                       // zeros visible everywhere

    for (int t = 0; t < 1024; t++) {
        // Prefetch input-side gates (latency hidden behind accumulate)
        float gxr = 0.f, gxz = 0.f, gxn = 0.f;
        if (tid < 256) {
            const float* gxp = g_gx + (size_t)(t * 64 + gb) * 1536 + j;
            gxr = gxp[0];
            gxz = gxp[512];
            gxn = gxp[1024];
        }

        if (t < maxlen_half) {      // warp-level ragged skip
            const float* hb = g_hT[t & 1] + (size_t)k0 * 64 + b0;
            unsigned long long accA[12], accB[12];
#pragma unroll
            for (int r = 0; r < 12; r++) { accA[r] = 0ull; accB[r] = 0ull; }

#pragma unroll
            for (int i = 0; i < 8; i++) {
                // 4 coalesced L2 loads: h_T[k..k+3][b0..b0+1]
                float2 hA = __ldcg((const float2*)(hb + (i * 4 + 0) * 64));
                float2 hB = __ldcg((const float2*)(hb + (i * 4 + 1) * 64));
                float2 hC = __ldcg((const float2*)(hb + (i * 4 + 2) * 64));
                float2 hD = __ldcg((const float2*)(hb + (i * 4 + 3) * 64));
                unsigned long long x0 = pack2(hA.x, hB.x);  // (k,k+1) for b0
                unsigned long long x1 = pack2(hA.y, hB.y);  // (k,k+1) for b0+1
                unsigned long long x2 = pack2(hC.x, hD.x);  // (k+2,k+3) for b0
                unsigned long long x3 = pack2(hC.y, hD.y);
#pragma unroll
                for (int r = 0; r < 12; r++) {
                    ulonglong2 wv = *(const ulonglong2*)&w_s[r][chunk][i * 4];
                    ffma2(accA[r], x0, wv.x);
                    ffma2(accA[r], x2, wv.y);
                    ffma2(accB[r], x1, wv.x);
                    ffma2(accB[r], x3, wv.y);
                }
            }

            // fold k-parity + k-sub (shfl xor 16), store per-(kslice) partials
#pragma unroll
            for (int r = 0; r < 12; r++) {
                float sA = sum2(accA[r]);
                float sB = sum2(accB[r]);
                sA += __shfl_xor_sync(0xffffffffu, sA, 16);
                sB += __shfl_xor_sync(0xffffffffu, sB, 16);
                if (ksub == 0) {
                    red[kslice][b0][r]     = sA;
                    red[kslice][b0 + 1][r] = sB;
                }
            }
        }
        __syncthreads();

        // Gate phase (tid < 256): reduce 8 k-slice partials, apply GRU cell
        if (tid < 256) {
            float outv = 0.f;
            if (t < len_b) {
                float ghr = bh_r, ghz = bh_z, ghn = bh_n;
#pragma unroll
                for (int ks = 0; ks < 8; ks++) {
                    ghr += red[ks][gb][gu];
                    ghz += red[ks][gb][4 + gu];
                    ghn += red[ks][gb][8 + gu];
                }
                float r = 1.f / (1.f + __expf(-(gxr + ghr)));
                float z = 1.f / (1.f + __expf(-(gxz + ghz)));
                float n = tanhf(gxn + r * ghn);
                float hnew = (1.f - z) * n + z * hreg;
                hreg = hnew;
                outv = hnew;
            }
            out[(size_t)t * 32768 + gb * 512 + j] = outv;
            __stcg(&g_hT[(t + 1) & 1][(size_t)j * 64 + gb], hreg);
        }

        grid_sync();   // h writes (L2) visible before next step reads
    }

    // h_last: [1, B, H] appended after output
    if (tid < 256)
        out[(size_t)1024 * 32768 + gb * 512 + j] = hreg;
}

// =================================================================================
// Inputs (metadata order): x[T,B,I] f32, batch_lengths[B] i32, w_ih[3H,I] f32,
// w_hh[3H,H] f32, b_ih[3H] f32, b_hh[3H] f32.  Output: [T,B,H] then [1,B,H], fp32.
// =================================================================================
extern "C" void kernel_launch(void* const* d_in, const int* in_sizes, int n_in,
                              void* d_out, int out_size) {
    const float* x   = (const float*)d_in[0];
    const int*   len = (const int*)  d_in[1];
    const float* wih = (const float*)d_in[2];
    const float* whh = (const float*)d_in[3];
    const float* bih = (const float*)d_in[4];
    const float* bhh = (const float*)d_in[5];
    float* out = (float*)d_out;

    (void)in_sizes; (void)n_in; (void)out_size;

    gemm_gx<<<dim3(12, 512), 256>>>(x, wih, bih);
    gru_rec<<<NCTA, 512>>>(whh, bhh, len, out);
}